// round 6
// baseline (speedup 1.0000x reference)
#include <cuda_runtime.h>
#include <math_constants.h>

#define BB 16
#define KK 256
#define ZZ 128
#define HH 128
#define BK (BB*KK)

typedef unsigned long long u64;

#define FMA2(d, a, b, c) \
  asm("fma.rn.f32x2 %0, %1, %2, %3;" : "=l"(d) : "l"(a), "l"(b), "l"(c))

__device__ __forceinline__ u64 pack2(float lo, float hi) {
  u64 r;
  asm("mov.b64 %0, {%1, %2};" : "=l"(r) : "f"(lo), "f"(hi));
  return r;
}
__device__ __forceinline__ void unpack2(u64 p, float& lo, float& hi) {
  asm("mov.b64 {%0, %1}, %2;" : "=f"(lo), "=f"(hi) : "l"(p));
}

// scratch (allocation-free: __device__ globals)
__device__ float g_m1[BK*ZZ];
__device__ float g_m2[BK*ZZ];
__device__ float g_mm[BK*ZZ];
// packed transposed weights: WT2[k][cp] = {W[2cp][k], W[2cp+1][k]}
__device__ u64 g_wt1[ZZ * (ZZ/2)];        // [128][64]
__device__ u64 g_wt2[ZZ * (ZZ/2)];        // [128][64]
__device__ u64 g_wtu[(2*ZZ) * (HH/2)];    // [256][64]

extern __shared__ u64 dynsmem[];

// ---------------------------------------------------------------------------
// Pack kernel: column-pair-packed transposed weights. grid=128, block=256.
// ---------------------------------------------------------------------------
__global__ __launch_bounds__(256) void pack_kernel(
    const float* __restrict__ W1, const float* __restrict__ W2,
    const float* __restrict__ Wu) {
  const int idx = blockIdx.x * 256 + threadIdx.x;
  if (idx < 8192) {
    const int k = idx & 127, cp = idx >> 7;
    g_wt1[k * 64 + cp] = pack2(W1[(2*cp)*ZZ + k], W1[(2*cp+1)*ZZ + k]);
  } else if (idx < 16384) {
    const int l = idx - 8192;
    const int k = l & 127, cp = l >> 7;
    g_wt2[k * 64 + cp] = pack2(W2[(2*cp)*ZZ + k], W2[(2*cp+1)*ZZ + k]);
  } else {
    const int l = idx - 16384;
    const int k = l & 255, cp = l >> 8;
    g_wtu[k * 64 + cp] = pack2(Wu[(2*cp)*(2*ZZ) + k], Wu[(2*cp+1)*(2*ZZ) + k]);
  }
}

// ---------------------------------------------------------------------------
// Kernel 1: y = x @ W^T + b, both weight sets. grid=(BK/32, 2), block=512.
// smem: sw[128k][64cp] (64KB) + sx[32row][128k] splat (32KB) = 96KB -> 2 blk/SM.
// Warp owns 2 rows; lane owns 4 cols (2 colpairs). Pure-smem inner loop.
// ---------------------------------------------------------------------------
__global__ __launch_bounds__(512) void lin_kernel(
    const float* __restrict__ z,
    const float* __restrict__ b1, const float* __restrict__ b2) {
  const u64*   WT   = blockIdx.y ? g_wt2 : g_wt1;
  const float* bias = blockIdx.y ? b2 : b1;
  float*       y    = blockIdx.y ? g_m2 : g_m1;

  u64* sw = dynsmem;               // [128][64]
  u64* sx = dynsmem + 128 * 64;    // [32][128]

  const int tid  = threadIdx.x;
  const int row0 = blockIdx.x * 32;

  // stage packed weights (64KB copy, coalesced 16B)
  {
    ulonglong2*       d = (ulonglong2*)sw;
    const ulonglong2* s = (const ulonglong2*)WT;
#pragma unroll
    for (int i = 0; i < 8; i++) d[i * 512 + tid] = s[i * 512 + tid];
  }
  // stage splatted activations (1024 float4)
  {
    const float4* zg = (const float4*)(z + row0 * ZZ);
#pragma unroll
    for (int i = 0; i < 2; i++) {
      const int idx = i * 512 + tid;
      const float4 v = zg[idx];
      u64* p = sx + (idx >> 5) * ZZ + (idx & 31) * 4;
      p[0] = pack2(v.x, v.x); p[1] = pack2(v.y, v.y);
      p[2] = pack2(v.z, v.z); p[3] = pack2(v.w, v.w);
    }
  }
  __syncthreads();

  const int lane = tid & 31;
  const int warp = tid >> 5;       // 0..15, owns rows warp*2, warp*2+1
  const u64* xb = sx + warp * 2 * ZZ;

  u64 acc[2][2];
#pragma unroll
  for (int r = 0; r < 2; r++) { acc[r][0] = 0ULL; acc[r][1] = 0ULL; }

#pragma unroll 8
  for (int k = 0; k < ZZ; k += 2) {
    const ulonglong2 wa = *(const ulonglong2*)(sw + k * 64 + lane * 2);
    const ulonglong2 wb = *(const ulonglong2*)(sw + (k + 1) * 64 + lane * 2);
#pragma unroll
    for (int r = 0; r < 2; r++) {
      const ulonglong2 xp = *(const ulonglong2*)(xb + r * ZZ + k);
      FMA2(acc[r][0], wa.x, xp.x, acc[r][0]);
      FMA2(acc[r][1], wa.y, xp.x, acc[r][1]);
      FMA2(acc[r][0], wb.x, xp.y, acc[r][0]);
      FMA2(acc[r][1], wb.y, xp.y, acc[r][1]);
    }
  }

  const float4 bv = ((const float4*)bias)[lane];
#pragma unroll
  for (int r = 0; r < 2; r++) {
    float a0, a1, a2, a3;
    unpack2(acc[r][0], a0, a1);
    unpack2(acc[r][1], a2, a3);
    const float4 o = make_float4(a0 + bv.x, a1 + bv.y, a2 + bv.z, a3 + bv.w);
    ((float4*)(y + (row0 + warp * 2 + r) * ZZ))[lane] = o;
  }
}

// ---------------------------------------------------------------------------
// Kernel 2: masked neighbor max + relu(m1 + max) -> g_mm
// grid = (K/64, B), block = 1024; warp handles 2 destination nodes.
// smem: 128KB m2 tile (dynamic) + 16KB adjacency bytes (static).
// ---------------------------------------------------------------------------
__global__ __launch_bounds__(1024) void maxagg_kernel(const int* __restrict__ P) {
  __shared__ unsigned char s_adj[KK * 64];  // [j][ii], 16KB

  float* s_m2 = (float*)dynsmem;
  const int b   = blockIdx.y;
  const int i0  = blockIdx.x * 64;
  const int tid = threadIdx.x;
  const int* Pb = P + b * KK * KK;

  // stage m2z[b] (coalesced float4)
  {
    float4*       s4 = (float4*)s_m2;
    const float4* g4 = (const float4*)(g_m2 + b * KK * ZZ);
#pragma unroll
    for (int c = 0; c < 8; c++) s4[c * 1024 + tid] = g4[c * 1024 + tid];
  }
  // stage adjacency bytes coalesced
#pragma unroll
  for (int c = 0; c < 16; c++) {
    const int idx = c * 1024 + tid;            // 0..16383
    s_adj[idx] = (Pb[(idx >> 6) * KK + i0 + (idx & 63)] != 0);
  }
  __syncthreads();

  const int warp = tid >> 5;
  const int lane = tid & 31;

  unsigned w0[8], w1[8];
#pragma unroll
  for (int wd = 0; wd < 8; wd++) {
    const unsigned char* row = &s_adj[(wd * 32 + lane) * 64];
    w0[wd] = __ballot_sync(0xFFFFFFFFu, row[warp] != 0);
    w1[wd] = __ballot_sync(0xFFFFFFFFu, row[32 + warp] != 0);
  }

  const float4* sm = (const float4*)s_m2;
  float4 acc0 = make_float4(-CUDART_INF_F, -CUDART_INF_F, -CUDART_INF_F, -CUDART_INF_F);
  float4 acc1 = acc0;

#pragma unroll
  for (int wd = 0; wd < 8; wd++) {
    const int base = wd * 32;
    unsigned word = w0[wd];
    while (word) {
      const int j = base + __ffs((int)word) - 1;
      word &= word - 1;
      const float4 v = sm[j * (ZZ / 4) + lane];
      acc0.x = fmaxf(acc0.x, v.x); acc0.y = fmaxf(acc0.y, v.y);
      acc0.z = fmaxf(acc0.z, v.z); acc0.w = fmaxf(acc0.w, v.w);
    }
    word = w1[wd];
    while (word) {
      const int j = base + __ffs((int)word) - 1;
      word &= word - 1;
      const float4 v = sm[j * (ZZ / 4) + lane];
      acc1.x = fmaxf(acc1.x, v.x); acc1.y = fmaxf(acc1.y, v.y);
      acc1.z = fmaxf(acc1.z, v.z); acc1.w = fmaxf(acc1.w, v.w);
    }
  }

  {
    const int ri = (b * KK + i0 + warp) * ZZ + lane * 4;
    const float4 m1 = *(const float4*)(g_m1 + ri);
    float4 o;
    o.x = fmaxf(m1.x + acc0.x, 0.0f); o.y = fmaxf(m1.y + acc0.y, 0.0f);
    o.z = fmaxf(m1.z + acc0.z, 0.0f); o.w = fmaxf(m1.w + acc0.w, 0.0f);
    *(float4*)(g_mm + ri) = o;
  }
  {
    const int ri = (b * KK + i0 + 32 + warp) * ZZ + lane * 4;
    const float4 m1 = *(const float4*)(g_m1 + ri);
    float4 o;
    o.x = fmaxf(m1.x + acc1.x, 0.0f); o.y = fmaxf(m1.y + acc1.y, 0.0f);
    o.z = fmaxf(m1.z + acc1.z, 0.0f); o.w = fmaxf(m1.w + acc1.w, 0.0f);
    *(float4*)(g_mm + ri) = o;
  }
}

// ---------------------------------------------------------------------------
// Kernel 3: out = relu([z, m] @ Wu^T + bu). grid=(BK/64, 2 colhalf), block=512.
// smem: sw k-pair interleaved (64KB) + sx[64][256] splat (128KB) = 192KB.
// Warp owns 4 rows; lane owns 1 colpair of its 64-col half.
// ---------------------------------------------------------------------------
__global__ __launch_bounds__(512) void out_kernel(
    const float* __restrict__ z,
    const float* __restrict__ bu, float* __restrict__ out) {
  u64* sw = dynsmem;               // u64 at (k>>1)*64 + cpl*2 + (k&1)
  u64* sx = dynsmem + 8192;        // [64][256]

  const int tid  = threadIdx.x;
  const int h    = blockIdx.y;       // column half
  const int row0 = blockIdx.x * 64;

  // stage weight half, k-pair interleaved (8192 u64)
#pragma unroll
  for (int c = 0; c < 16; c++) {
    const int idx = c * 512 + tid;
    const int k = idx >> 5, cpl = idx & 31;
    sw[(k >> 1) * 64 + cpl * 2 + (k & 1)] = g_wtu[k * 64 + h * 32 + cpl];
  }
  // stage splatted [z | m] tile (2048 float4 each source)
  {
    const float4* zg = (const float4*)(z + row0 * ZZ);
    const float4* mg = (const float4*)(g_mm + row0 * ZZ);
#pragma unroll
    for (int c = 0; c < 4; c++) {
      const int idx = c * 512 + tid;
      const int r = idx >> 5, k4 = (idx & 31) * 4;
      const float4 v = zg[idx];
      u64* p = sx + r * 256 + k4;
      p[0] = pack2(v.x, v.x); p[1] = pack2(v.y, v.y);
      p[2] = pack2(v.z, v.z); p[3] = pack2(v.w, v.w);
      const float4 m = mg[idx];
      u64* q = p + ZZ;
      q[0] = pack2(m.x, m.x); q[1] = pack2(m.y, m.y);
      q[2] = pack2(m.z, m.z); q[3] = pack2(m.w, m.w);
    }
  }
  __syncthreads();

  const int lane = tid & 31;
  const int warp = tid >> 5;        // 0..15, owns rows warp*4..+3
  const u64* xb = sx + warp * 4 * 256;

  u64 acc[4];
#pragma unroll
  for (int r = 0; r < 4; r++) acc[r] = 0ULL;

#pragma unroll 8
  for (int kk = 0; kk < 128; kk++) {   // two k per iter
    const ulonglong2 w2 = *(const ulonglong2*)(sw + kk * 64 + lane * 2);
#pragma unroll
    for (int r = 0; r < 4; r++) {
      const ulonglong2 xp = *(const ulonglong2*)(xb + r * 256 + kk * 2);
      FMA2(acc[r], w2.x, xp.x, acc[r]);
      FMA2(acc[r], w2.y, xp.y, acc[r]);
    }
  }

  const float2 bv = ((const float2*)bu)[h * 32 + lane];
#pragma unroll
  for (int r = 0; r < 4; r++) {
    float a0, a1;
    unpack2(acc[r], a0, a1);
    float2 o;
    o.x = fmaxf(a0 + bv.x, 0.0f);
    o.y = fmaxf(a1 + bv.y, 0.0f);
    ((float2*)(out + (row0 + warp * 4 + r) * HH + h * 64))[lane] = o;
  }
}

// ---------------------------------------------------------------------------
extern "C" void kernel_launch(void* const* d_in, const int* in_sizes, int n_in,
                              void* d_out, int out_size) {
  const float* z  = (const float*)d_in[0];
  const int*   P  = (const int*)  d_in[1];
  const float* W1 = (const float*)d_in[2];
  const float* b1 = (const float*)d_in[3];
  const float* W2 = (const float*)d_in[4];
  const float* b2 = (const float*)d_in[5];
  const float* Wu = (const float*)d_in[6];
  const float* bu = (const float*)d_in[7];
  float* out = (float*)d_out;

  (void)cudaFuncSetAttribute(lin_kernel, cudaFuncAttributeMaxDynamicSharedMemorySize, 98304);
  (void)cudaFuncSetAttribute(maxagg_kernel, cudaFuncAttributeMaxDynamicSharedMemorySize, 131072);
  (void)cudaFuncSetAttribute(out_kernel, cudaFuncAttributeMaxDynamicSharedMemorySize, 196608);

  pack_kernel<<<128, 256>>>(W1, W2, Wu);
  lin_kernel<<<dim3(BK / 32, 2), 512, 98304>>>(z, b1, b2);
  maxagg_kernel<<<dim3(KK / 64, BB), 1024, KK * ZZ * sizeof(float)>>>(P);
  out_kernel<<<dim3(BK / 64, 2), 512, 196608>>>(z, bu, out);
}

// round 9
// speedup vs baseline: 1.5336x; 1.5336x over previous
#include <cuda_runtime.h>
#include <math_constants.h>

#define BB 16
#define KK 256
#define ZZ 128
#define HH 128
#define BK (BB*KK)

typedef unsigned long long u64;

#define FMA2(d, a, b, c) \
  asm("fma.rn.f32x2 %0, %1, %2, %3;" : "=l"(d) : "l"(a), "l"(b), "l"(c))

__device__ __forceinline__ u64 pack2(float lo, float hi) {
  u64 r;
  asm("mov.b64 %0, {%1, %2};" : "=l"(r) : "f"(lo), "f"(hi));
  return r;
}
__device__ __forceinline__ float sum2(u64 p) {
  float lo, hi;
  asm("mov.b64 {%0, %1}, %2;" : "=f"(lo), "=f"(hi) : "l"(p));
  return lo + hi;
}

// scratch (allocation-free: __device__ globals)
__device__ float g_m1[BK*ZZ];
__device__ float g_m2[BK*ZZ];
__device__ float g_mm[BK*ZZ];
// k-pair-packed transposed weights: WT[kp*NC + c] = {W[c][2kp], W[c][2kp+1]}
__device__ u64 g_wt1[64 * ZZ];     // [64 kp][128 c]
__device__ u64 g_wt2[64 * ZZ];     // [64 kp][128 c]
__device__ u64 g_wtu[128 * HH];    // [128 kp][128 c]

extern __shared__ u64 dynsmem[];

// ---------------------------------------------------------------------------
// Pack kernel: k-pair-packed transposed weights. grid=128, block=256.
// ---------------------------------------------------------------------------
__global__ __launch_bounds__(256) void pack_kernel(
    const float* __restrict__ W1, const float* __restrict__ W2,
    const float* __restrict__ Wu) {
  const int idx = blockIdx.x * 256 + threadIdx.x;
  if (idx < 8192) {
    const int kp = idx >> 7, c = idx & 127;
    g_wt1[kp * ZZ + c] = pack2(W1[c * ZZ + 2*kp], W1[c * ZZ + 2*kp + 1]);
  } else if (idx < 16384) {
    const int l = idx - 8192;
    const int kp = l >> 7, c = l & 127;
    g_wt2[kp * ZZ + c] = pack2(W2[c * ZZ + 2*kp], W2[c * ZZ + 2*kp + 1]);
  } else {
    const int l = idx - 16384;            // 0..16383
    const int kp = l >> 7, c = l & 127;
    g_wtu[kp * HH + c] = pack2(Wu[c * (2*ZZ) + 2*kp], Wu[c * (2*ZZ) + 2*kp + 1]);
  }
}

// ---------------------------------------------------------------------------
// Kernel 1: y = x @ W^T + b, both weight sets. grid=(BK/32, 2 wsets), block=256.
// smem: sw[64kp][128c] u64 (64KB) + sx[32r][128k] fp32 (16KB) = 80KB -> 2 blk/SM.
// Warp = 8 rows x 64 cols (rowgroup warp>>1, col half warp&1); lane owns 2 cols.
// acc u64 = {even-k sum, odd-k sum}; horizontal add at the end.
// ---------------------------------------------------------------------------
__global__ __launch_bounds__(256) void lin_kernel(
    const float* __restrict__ z,
    const float* __restrict__ b1, const float* __restrict__ b2) {
  const u64*   WT   = blockIdx.y ? g_wt2 : g_wt1;
  const float* bias = blockIdx.y ? b2 : b1;
  float*       y    = blockIdx.y ? g_m2 : g_m1;

  u64*   sw = dynsmem;                    // [64][128]
  float* sx = (float*)(dynsmem + 64 * ZZ); // [32][128]

  const int tid  = threadIdx.x;
  const int row0 = blockIdx.x * 32;

  // stage packed weights (64KB, coalesced 16B)
  {
    ulonglong2*       d = (ulonglong2*)sw;
    const ulonglong2* s = (const ulonglong2*)WT;
#pragma unroll
    for (int i = 0; i < 16; i++) d[i * 256 + tid] = s[i * 256 + tid];
  }
  // stage raw activations (1024 float4)
  {
    float4*       d = (float4*)sx;
    const float4* s = (const float4*)(z + row0 * ZZ);
#pragma unroll
    for (int i = 0; i < 4; i++) d[i * 256 + tid] = s[i * 256 + tid];
  }
  __syncthreads();

  const int lane = tid & 31;
  const int warp = tid >> 5;
  const int rg   = warp >> 1;             // row group 0..3 (8 rows)
  const int h    = warp & 1;              // col half 0..1 (64 cols)
  const float* xb = sx + rg * 8 * ZZ;
  const u64*   wb = sw + h * 64 + lane * 2;

  u64 acc[8][2];
#pragma unroll
  for (int r = 0; r < 8; r++) { acc[r][0] = 0ULL; acc[r][1] = 0ULL; }

#pragma unroll 4
  for (int kp2 = 0; kp2 < 32; kp2++) {    // 4 k per iter
    const ulonglong2 wa = *(const ulonglong2*)(wb + (2*kp2)     * ZZ);
    const ulonglong2 wc = *(const ulonglong2*)(wb + (2*kp2 + 1) * ZZ);
#pragma unroll
    for (int r = 0; r < 8; r++) {
      const ulonglong2 xq = *(const ulonglong2*)(xb + r * ZZ + 4*kp2); // broadcast
      FMA2(acc[r][0], wa.x, xq.x, acc[r][0]);
      FMA2(acc[r][1], wa.y, xq.x, acc[r][1]);
      FMA2(acc[r][0], wc.x, xq.y, acc[r][0]);
      FMA2(acc[r][1], wc.y, xq.y, acc[r][1]);
    }
  }

  const float2 bv = ((const float2*)bias)[h * 32 + lane];
#pragma unroll
  for (int r = 0; r < 8; r++) {
    float2 o;
    o.x = sum2(acc[r][0]) + bv.x;
    o.y = sum2(acc[r][1]) + bv.y;
    ((float2*)(y + (row0 + rg * 8 + r) * ZZ + h * 64))[lane] = o;
  }
}

// ---------------------------------------------------------------------------
// Kernel 2: masked neighbor max + relu(m1 + max) -> g_mm  (R5 proven config)
// grid = (K/32, B), block = 1024 (warp = destination node i).
// ---------------------------------------------------------------------------
__global__ __launch_bounds__(1024) void maxagg_kernel(const int* __restrict__ P) {
  __shared__ unsigned char s_adj[KK * 32];  // 8KB

  float* s_m2 = (float*)dynsmem;
  const int b   = blockIdx.y;
  const int i0  = blockIdx.x * 32;
  const int tid = threadIdx.x;
  const int* Pb = P + b * KK * KK;

  {
    float4*       s4 = (float4*)s_m2;
    const float4* g4 = (const float4*)(g_m2 + b * KK * ZZ);
#pragma unroll
    for (int c = 0; c < 8; c++) s4[c * 1024 + tid] = g4[c * 1024 + tid];
  }
#pragma unroll
  for (int c = 0; c < 8; c++) {
    const int idx = c * 1024 + tid;
    s_adj[idx] = (Pb[(idx >> 5) * KK + i0 + (idx & 31)] != 0);
  }
  __syncthreads();

  const int warp = tid >> 5;
  const int lane = tid & 31;
  const int i    = i0 + warp;

  unsigned words[8];
#pragma unroll
  for (int wd = 0; wd < 8; wd++) {
    const unsigned pv = s_adj[(wd * 32 + lane) * 32 + warp];
    words[wd] = __ballot_sync(0xFFFFFFFFu, pv != 0);
  }

  float4 acc = make_float4(-CUDART_INF_F, -CUDART_INF_F, -CUDART_INF_F, -CUDART_INF_F);
  const float4* sm = (const float4*)s_m2;

#pragma unroll
  for (int wd = 0; wd < 8; wd++) {
    unsigned word = words[wd];
    const int base = wd * 32;
    while (word) {
      const int j = base + __ffs((int)word) - 1;
      word &= word - 1;
      const float4 v = sm[j * (ZZ / 4) + lane];
      acc.x = fmaxf(acc.x, v.x);
      acc.y = fmaxf(acc.y, v.y);
      acc.z = fmaxf(acc.z, v.z);
      acc.w = fmaxf(acc.w, v.w);
    }
  }

  const int ri = (b * KK + i) * ZZ + lane * 4;
  const float4 m1 = *(const float4*)(g_m1 + ri);
  float4 o;
  o.x = fmaxf(m1.x + acc.x, 0.0f);
  o.y = fmaxf(m1.y + acc.y, 0.0f);
  o.z = fmaxf(m1.z + acc.z, 0.0f);
  o.w = fmaxf(m1.w + acc.w, 0.0f);
  *(float4*)(g_mm + ri) = o;
}

// ---------------------------------------------------------------------------
// Kernel 3: out = relu([z, m] @ Wu^T + bu). grid=(BK/32, 2 colhalf), block=256.
// smem: sw[128kp][64c] u64 (64KB) + sx[32r][256k] fp32 (32KB) = 96KB -> 2 blk/SM.
// Warp = 4 rows x 64 cols; lane owns 2 cols.
// ---------------------------------------------------------------------------
__global__ __launch_bounds__(256) void out_kernel(
    const float* __restrict__ z,
    const float* __restrict__ bu, float* __restrict__ out) {
  u64*   sw = dynsmem;                      // [128][64]
  float* sx = (float*)(dynsmem + 128 * 64); // [32][256]

  const int tid  = threadIdx.x;
  const int h    = blockIdx.y;              // column half (64 cols)
  const int row0 = blockIdx.x * 32;

  // stage weight half: sw[kp*64 + cl] = g_wtu[kp*128 + h*64 + cl]  (8192 u64)
#pragma unroll
  for (int i = 0; i < 32; i++) {
    const int idx = i * 256 + tid;          // 0..8191
    const int kp = idx >> 6, cl = idx & 63;
    sw[idx] = g_wtu[kp * HH + h * 64 + cl];
  }
  // stage raw [z | m] tile: 32 rows x 256 floats (2048 float4)
  {
    const float4* zg = (const float4*)(z + row0 * ZZ);
    const float4* mg = (const float4*)(g_mm + row0 * ZZ);
#pragma unroll
    for (int i = 0; i < 4; i++) {
      const int idx = i * 256 + tid;        // 0..1023 (row r, chunk c of 32)
      const int r = idx >> 5, c = idx & 31;
      ((float4*)sx)[r * 64 + c]      = zg[idx];
      ((float4*)sx)[r * 64 + 32 + c] = mg[idx];
    }
  }
  __syncthreads();

  const int lane = tid & 31;
  const int warp = tid >> 5;                // row group 0..7 (4 rows)
  const float* xb = sx + warp * 4 * 256;
  const u64*   wb = sw + lane * 2;

  u64 acc[4][2];
#pragma unroll
  for (int r = 0; r < 4; r++) { acc[r][0] = 0ULL; acc[r][1] = 0ULL; }

#pragma unroll 8
  for (int kp2 = 0; kp2 < 64; kp2++) {      // 4 k per iter
    const ulonglong2 wa = *(const ulonglong2*)(wb + (2*kp2)     * 64);
    const ulonglong2 wc = *(const ulonglong2*)(wb + (2*kp2 + 1) * 64);
#pragma unroll
    for (int r = 0; r < 4; r++) {
      const ulonglong2 xq = *(const ulonglong2*)(xb + r * 256 + 4*kp2); // broadcast
      FMA2(acc[r][0], wa.x, xq.x, acc[r][0]);
      FMA2(acc[r][1], wa.y, xq.x, acc[r][1]);
      FMA2(acc[r][0], wc.x, xq.y, acc[r][0]);
      FMA2(acc[r][1], wc.y, xq.y, acc[r][1]);
    }
  }

  const float2 bv = ((const float2*)bu)[h * 32 + lane];
#pragma unroll
  for (int r = 0; r < 4; r++) {
    float2 o;
    o.x = fmaxf(sum2(acc[r][0]) + bv.x, 0.0f);
    o.y = fmaxf(sum2(acc[r][1]) + bv.y, 0.0f);
    ((float2*)(out + (row0 + warp * 4 + r) * HH + h * 64))[lane] = o;
  }
}

// ---------------------------------------------------------------------------
extern "C" void kernel_launch(void* const* d_in, const int* in_sizes, int n_in,
                              void* d_out, int out_size) {
  const float* z  = (const float*)d_in[0];
  const int*   P  = (const int*)  d_in[1];
  const float* W1 = (const float*)d_in[2];
  const float* b1 = (const float*)d_in[3];
  const float* W2 = (const float*)d_in[4];
  const float* b2 = (const float*)d_in[5];
  const float* Wu = (const float*)d_in[6];
  const float* bu = (const float*)d_in[7];
  float* out = (float*)d_out;

  (void)cudaFuncSetAttribute(lin_kernel, cudaFuncAttributeMaxDynamicSharedMemorySize, 81920);
  (void)cudaFuncSetAttribute(maxagg_kernel, cudaFuncAttributeMaxDynamicSharedMemorySize, 131072);
  (void)cudaFuncSetAttribute(out_kernel, cudaFuncAttributeMaxDynamicSharedMemorySize, 98304);

  pack_kernel<<<128, 256>>>(W1, W2, Wu);
  lin_kernel<<<dim3(BK / 32, 2), 256, 81920>>>(z, b1, b2);
  maxagg_kernel<<<dim3(KK / 32, BB), 1024, KK * ZZ * sizeof(float)>>>(P);
  out_kernel<<<dim3(BK / 32, 2), 256, 98304>>>(z, bu, out);
}

// round 10
// speedup vs baseline: 1.6029x; 1.0452x over previous
#include <cuda_runtime.h>
#include <cuda_fp16.h>
#include <math_constants.h>

#define BB 16
#define KK 256
#define ZZ 128
#define HH 128
#define BK (BB*KK)

typedef unsigned long long u64;

#define FMA2(d, a, b, c) \
  asm("fma.rn.f32x2 %0, %1, %2, %3;" : "=l"(d) : "l"(a), "l"(b), "l"(c))

__device__ __forceinline__ u64 pack2(float lo, float hi) {
  u64 r;
  asm("mov.b64 %0, {%1, %2};" : "=l"(r) : "f"(lo), "f"(hi));
  return r;
}
__device__ __forceinline__ float sum2(u64 p) {
  float lo, hi;
  asm("mov.b64 {%0, %1}, %2;" : "=f"(lo), "=f"(hi) : "l"(p));
  return lo + hi;
}

// scratch (allocation-free: __device__ globals)
__device__ float  g_m1[BK*ZZ];
__device__ float  g_m2[BK*ZZ];
__device__ __half2 g_m2h[BK*64];   // fp16 mirror of m2 for the max pass
__device__ float  g_mm[BK*ZZ];
// k-pair-packed transposed weights: WT[kp*NC + c] = {W[c][2kp], W[c][2kp+1]}
__device__ u64 g_wt1[64 * ZZ];     // [64 kp][128 c]
__device__ u64 g_wt2[64 * ZZ];     // [64 kp][128 c]
__device__ u64 g_wtu[128 * HH];    // [128 kp][128 c]

extern __shared__ __align__(16) u64 dynsmem[];

// ---------------------------------------------------------------------------
// Pack kernel: k-pair-packed transposed weights. grid=128, block=256.
// ---------------------------------------------------------------------------
__global__ __launch_bounds__(256) void pack_kernel(
    const float* __restrict__ W1, const float* __restrict__ W2,
    const float* __restrict__ Wu) {
  const int idx = blockIdx.x * 256 + threadIdx.x;
  if (idx < 8192) {
    const int kp = idx >> 7, c = idx & 127;
    g_wt1[kp * ZZ + c] = pack2(W1[c * ZZ + 2*kp], W1[c * ZZ + 2*kp + 1]);
  } else if (idx < 16384) {
    const int l = idx - 8192;
    const int kp = l >> 7, c = l & 127;
    g_wt2[kp * ZZ + c] = pack2(W2[c * ZZ + 2*kp], W2[c * ZZ + 2*kp + 1]);
  } else {
    const int l = idx - 16384;
    const int kp = l >> 7, c = l & 127;
    g_wtu[kp * HH + c] = pack2(Wu[c * (2*ZZ) + 2*kp], Wu[c * (2*ZZ) + 2*kp + 1]);
  }
}

// ---------------------------------------------------------------------------
// Kernel 1: y = x @ W^T + b, both weight sets. grid=(BK/64, 2 wsets), block=512.
// smem: sw[64kp][128c] u64 (64KB) + sx[64r][128k] fp32 (32KB) = 96KB.
// Warp = 8 rows x 64 cols (rg=warp>>1, h=warp&1); lane owns 2 cols.
// Register-prefetched weights; batched x loads. m2 also emitted as fp16.
// ---------------------------------------------------------------------------
__global__ __launch_bounds__(512) void lin_kernel(
    const float* __restrict__ z,
    const float* __restrict__ b1, const float* __restrict__ b2) {
  const u64*   WT   = blockIdx.y ? g_wt2 : g_wt1;
  const float* bias = blockIdx.y ? b2 : b1;
  float*       y    = blockIdx.y ? g_m2 : g_m1;

  u64*   sw = dynsmem;                      // [64][128]
  float* sx = (float*)(dynsmem + 64 * ZZ);  // [64][128]

  const int tid  = threadIdx.x;
  const int row0 = blockIdx.x * 64;

  // stage packed weights (64KB, coalesced 16B)
  {
    ulonglong2*       d = (ulonglong2*)sw;
    const ulonglong2* s = (const ulonglong2*)WT;
#pragma unroll
    for (int i = 0; i < 8; i++) d[i * 512 + tid] = s[i * 512 + tid];
  }
  // stage raw activations (2048 float4)
  {
    float4*       d = (float4*)sx;
    const float4* s = (const float4*)(z + row0 * ZZ);
#pragma unroll
    for (int i = 0; i < 4; i++) d[i * 512 + tid] = s[i * 512 + tid];
  }
  __syncthreads();

  const int lane = tid & 31;
  const int warp = tid >> 5;
  const int rg   = warp >> 1;               // row group 0..7 (8 rows)
  const int h    = warp & 1;                // col half
  const float* xb = sx + rg * 8 * ZZ;
  const u64*   wb = sw + h * 64 + lane * 2;

  u64 acc[8][2];
#pragma unroll
  for (int r = 0; r < 8; r++) { acc[r][0] = 0ULL; acc[r][1] = 0ULL; }

  ulonglong2 wa = *(const ulonglong2*)(wb);
  ulonglong2 wc = *(const ulonglong2*)(wb + ZZ);

#pragma unroll 4
  for (int kp2 = 0; kp2 < 32; kp2++) {      // 4 k per iter
    const int nxt = (kp2 + 1) & 31;
    const ulonglong2 wa_n = *(const ulonglong2*)(wb + (2*nxt)     * ZZ);
    const ulonglong2 wc_n = *(const ulonglong2*)(wb + (2*nxt + 1) * ZZ);
    ulonglong2 xq[8];
#pragma unroll
    for (int r = 0; r < 8; r++)
      xq[r] = *(const ulonglong2*)(xb + r * ZZ + 4*kp2);   // broadcast
#pragma unroll
    for (int r = 0; r < 8; r++) {
      FMA2(acc[r][0], wa.x, xq[r].x, acc[r][0]);
      FMA2(acc[r][1], wa.y, xq[r].x, acc[r][1]);
      FMA2(acc[r][0], wc.x, xq[r].y, acc[r][0]);
      FMA2(acc[r][1], wc.y, xq[r].y, acc[r][1]);
    }
    wa = wa_n; wc = wc_n;
  }

  const float2 bv = ((const float2*)bias)[h * 32 + lane];
  const int wr = blockIdx.y;
#pragma unroll
  for (int r = 0; r < 8; r++) {
    const int row = row0 + rg * 8 + r;
    float2 o;
    o.x = sum2(acc[r][0]) + bv.x;
    o.y = sum2(acc[r][1]) + bv.y;
    ((float2*)(y + row * ZZ + h * 64))[lane] = o;
    if (wr) g_m2h[row * 64 + h * 32 + lane] = __float22half2_rn(o);
  }
}

// ---------------------------------------------------------------------------
// Kernel 2: masked neighbor max (fp16) + relu(m1 + max) -> g_mm (fp32)
// grid = (K/16, B), block = 512 (warp = one destination node i).
// smem: 64KB fp16 m2 tile (dynamic) + 4KB adjacency bytes (static).
// max over fp16-rounded values == fp16(true max): rounding is monotone.
// ---------------------------------------------------------------------------
__global__ __launch_bounds__(512) void maxagg_kernel(const int* __restrict__ P) {
  __shared__ unsigned char s_adj[KK * 16];  // 4KB

  uint2* sh = (uint2*)dynsmem;              // [256 rows][32 lanes] uint2 (4 halves)
  const int b   = blockIdx.y;
  const int i0  = blockIdx.x * 16;
  const int tid = threadIdx.x;
  const int* Pb = P + b * KK * KK;

  // stage fp16 m2 tile (4096 uint4, coalesced)
  {
    uint4*       d = (uint4*)sh;
    const uint4* s = (const uint4*)(g_m2h + (size_t)b * KK * 64);
#pragma unroll
    for (int c = 0; c < 8; c++) d[c * 512 + tid] = s[c * 512 + tid];
  }
  // stage adjacency bytes (coalesced)
#pragma unroll
  for (int c = 0; c < 8; c++) {
    const int idx = c * 512 + tid;          // 0..4095
    s_adj[idx] = (Pb[(idx >> 4) * KK + i0 + (idx & 15)] != 0);
  }
  __syncthreads();

  const int warp = tid >> 5;
  const int lane = tid & 31;
  const int i    = i0 + warp;

  unsigned words[8];
#pragma unroll
  for (int wd = 0; wd < 8; wd++) {
    const unsigned pv = s_adj[(wd * 32 + lane) * 16 + warp];
    words[wd] = __ballot_sync(0xFFFFFFFFu, pv != 0);
  }

  const __half2 ninf = __half2half2(__ushort_as_half(0xFC00));  // -inf
  __half2 a0 = ninf, a1 = ninf;
  const uint2* row = sh + lane;

#pragma unroll
  for (int wd = 0; wd < 8; wd++) {
    unsigned word = words[wd];
    const int base = wd * 32;
    while (word) {                          // warp-uniform: only active neighbors
      const int j = base + __ffs((int)word) - 1;
      word &= word - 1;
      const uint2 v = row[j * 32];          // 4 halves, 256B/warp = 2 wavefronts
      a0 = __hmax2(a0, *(const __half2*)&v.x);
      a1 = __hmax2(a1, *(const __half2*)&v.y);
    }
  }

  const float2 f0 = __half22float2(a0);
  const float2 f1 = __half22float2(a1);
  const int ri = (b * KK + i) * ZZ + lane * 4;
  const float4 m1 = *(const float4*)(g_m1 + ri);
  float4 o;
  o.x = fmaxf(m1.x + f0.x, 0.0f);
  o.y = fmaxf(m1.y + f0.y, 0.0f);
  o.z = fmaxf(m1.z + f1.x, 0.0f);
  o.w = fmaxf(m1.w + f1.y, 0.0f);
  *(float4*)(g_mm + ri) = o;
}

// ---------------------------------------------------------------------------
// Kernel 3: out = relu([z, m] @ Wu^T + bu). grid=(BK/64, 2 colhalf), block=256.
// smem: sw[128kp][64c] u64 (64KB) + sx[64r][256k] fp32 (64KB) = 128KB.
// Warp = 8 rows x 64 cols; lane owns 2 cols. Prefetched weights, batched x.
// ---------------------------------------------------------------------------
__global__ __launch_bounds__(256) void out_kernel(
    const float* __restrict__ z,
    const float* __restrict__ bu, float* __restrict__ out) {
  u64*   sw = dynsmem;                      // [128][64]
  float* sx = (float*)(dynsmem + 128 * 64); // [64][256]

  const int tid  = threadIdx.x;
  const int h    = blockIdx.y;              // column half (64 cols)
  const int row0 = blockIdx.x * 64;

  // stage weight half (8192 u64, coalesced 512B runs)
#pragma unroll
  for (int i = 0; i < 32; i++) {
    const int idx = i * 256 + tid;
    const int kp = idx >> 6, cl = idx & 63;
    sw[idx] = g_wtu[kp * HH + h * 64 + cl];
  }
  // stage raw [z | m] tile: 64 rows x 256 floats (2048 float4 per source)
  {
    const float4* zg = (const float4*)(z + row0 * ZZ);
    const float4* mg = (const float4*)(g_mm + row0 * ZZ);
#pragma unroll
    for (int i = 0; i < 8; i++) {
      const int idx = i * 256 + tid;        // 0..2047: row r, chunk c of 32
      const int r = idx >> 5, c = idx & 31;
      ((float4*)sx)[r * 64 + c]      = zg[idx];
      ((float4*)sx)[r * 64 + 32 + c] = mg[idx];
    }
  }
  __syncthreads();

  const int lane = tid & 31;
  const int warp = tid >> 5;                // row group 0..7 (8 rows)
  const float* xb = sx + warp * 8 * 256;
  const u64*   wb = sw + lane * 2;

  u64 acc[8][2];
#pragma unroll
  for (int r = 0; r < 8; r++) { acc[r][0] = 0ULL; acc[r][1] = 0ULL; }

  ulonglong2 wa = *(const ulonglong2*)(wb);
  ulonglong2 wc = *(const ulonglong2*)(wb + 64);

#pragma unroll 2
  for (int kp2 = 0; kp2 < 64; kp2++) {      // 4 k per iter
    const int nxt = (kp2 + 1) & 63;
    const ulonglong2 wa_n = *(const ulonglong2*)(wb + (2*nxt)     * 64);
    const ulonglong2 wc_n = *(const ulonglong2*)(wb + (2*nxt + 1) * 64);
    ulonglong2 xq[8];
#pragma unroll
    for (int r = 0; r < 8; r++)
      xq[r] = *(const ulonglong2*)(xb + r * 256 + 4*kp2);  // broadcast
#pragma unroll
    for (int r = 0; r < 8; r++) {
      FMA2(acc[r][0], wa.x, xq[r].x, acc[r][0]);
      FMA2(acc[r][1], wa.y, xq[r].x, acc[r][1]);
      FMA2(acc[r][0], wc.x, xq[r].y, acc[r][0]);
      FMA2(acc[r][1], wc.y, xq[r].y, acc[r][1]);
    }
    wa = wa_n; wc = wc_n;
  }

  const float2 bv = ((const float2*)bu)[h * 32 + lane];
#pragma unroll
  for (int r = 0; r < 8; r++) {
    float2 o;
    o.x = fmaxf(sum2(acc[r][0]) + bv.x, 0.0f);
    o.y = fmaxf(sum2(acc[r][1]) + bv.y, 0.0f);
    ((float2*)(out + (row0 + warp * 8 + r) * HH + h * 64))[lane] = o;
  }
}

// ---------------------------------------------------------------------------
extern "C" void kernel_launch(void* const* d_in, const int* in_sizes, int n_in,
                              void* d_out, int out_size) {
  const float* z  = (const float*)d_in[0];
  const int*   P  = (const int*)  d_in[1];
  const float* W1 = (const float*)d_in[2];
  const float* b1 = (const float*)d_in[3];
  const float* W2 = (const float*)d_in[4];
  const float* b2 = (const float*)d_in[5];
  const float* Wu = (const float*)d_in[6];
  const float* bu = (const float*)d_in[7];
  float* out = (float*)d_out;

  (void)cudaFuncSetAttribute(lin_kernel, cudaFuncAttributeMaxDynamicSharedMemorySize, 98304);
  (void)cudaFuncSetAttribute(maxagg_kernel, cudaFuncAttributeMaxDynamicSharedMemorySize, 65536);
  (void)cudaFuncSetAttribute(out_kernel, cudaFuncAttributeMaxDynamicSharedMemorySize, 131072);

  pack_kernel<<<128, 256>>>(W1, W2, Wu);
  lin_kernel<<<dim3(BK / 64, 2), 512, 98304>>>(z, b1, b2);
  maxagg_kernel<<<dim3(KK / 16, BB), 512, 65536>>>(P);
  out_kernel<<<dim3(BK / 64, 2), 256, 131072>>>(z, bu, out);
}